// round 1
// baseline (speedup 1.0000x reference)
#include <cuda_runtime.h>
#include <cuda_bf16.h>

// GraphGather / segment_sum:
//   out[b, f] = sum over atoms a with membership[a]==b of feats[a, f]
// feats: [524288, 128] f32, membership: [524288] i32 (SORTED), out: [16384, 128] f32.
//
// membership is sorted -> each segment is a contiguous run of rows.
// One warp handles ROWS_PER_WARP consecutive rows; lane l owns features
// [4l, 4l+4) as a float4. Accumulate in registers across the run; flush
// with atomicAdd (REDG) only on segment change / range end.

#define N_FEAT 128
#define ROWS_PER_WARP 32
#define THREADS_PER_BLOCK 256

__global__ void gg_zero_kernel(float* __restrict__ out, int n) {
    int i = blockIdx.x * blockDim.x + threadIdx.x;
    if (i < n) out[i] = 0.0f;
}

__global__ __launch_bounds__(THREADS_PER_BLOCK)
void gg_segsum_kernel(const float4* __restrict__ feats,
                      const int* __restrict__ memb,
                      float* __restrict__ out,
                      int n_atoms) {
    const int warp_id = (blockIdx.x * THREADS_PER_BLOCK + threadIdx.x) >> 5;
    const int lane = threadIdx.x & 31;

    long long row0 = (long long)warp_id * ROWS_PER_WARP;
    if (row0 >= n_atoms) return;
    long long row_end = row0 + ROWS_PER_WARP;
    if (row_end > n_atoms) row_end = n_atoms;

    float4 acc = make_float4(0.f, 0.f, 0.f, 0.f);
    int cur = memb[row0];

    #pragma unroll 4
    for (long long r = row0; r < row_end; ++r) {
        // Independent loads per iteration -> high MLP; membership read is a
        // warp-uniform broadcast (L1 hit after first lane).
        int m = memb[r];
        float4 v = feats[r * (N_FEAT / 4) + lane];

        if (m != cur) {
            float* o = out + (long long)cur * N_FEAT + lane * 4;
            atomicAdd(o + 0, acc.x);
            atomicAdd(o + 1, acc.y);
            atomicAdd(o + 2, acc.z);
            atomicAdd(o + 3, acc.w);
            acc = make_float4(0.f, 0.f, 0.f, 0.f);
            cur = m;
        }
        acc.x += v.x;
        acc.y += v.y;
        acc.z += v.z;
        acc.w += v.w;
    }

    // Final flush for this warp's range.
    float* o = out + (long long)cur * N_FEAT + lane * 4;
    atomicAdd(o + 0, acc.x);
    atomicAdd(o + 1, acc.y);
    atomicAdd(o + 2, acc.z);
    atomicAdd(o + 3, acc.w);
}

extern "C" void kernel_launch(void* const* d_in, const int* in_sizes, int n_in,
                              void* d_out, int out_size) {
    const float* feats = (const float*)d_in[0];
    const int* memb = (const int*)d_in[1];
    float* out = (float*)d_out;

    const int n_atoms = in_sizes[1];          // 524288
    const int out_elems = out_size;           // 16384 * 128 = 2097152

    // Zero the (0xAA-poisoned) output first.
    {
        int threads = 256;
        int blocks = (out_elems + threads - 1) / threads;
        gg_zero_kernel<<<blocks, threads>>>(out, out_elems);
    }

    // Main segment-sum: one warp per ROWS_PER_WARP rows.
    {
        int n_warps = (n_atoms + ROWS_PER_WARP - 1) / ROWS_PER_WARP;
        int warps_per_block = THREADS_PER_BLOCK / 32;
        int blocks = (n_warps + warps_per_block - 1) / warps_per_block;
        gg_segsum_kernel<<<blocks, THREADS_PER_BLOCK>>>(
            (const float4*)feats, memb, out, n_atoms);
    }
}

// round 2
// speedup vs baseline: 1.0298x; 1.0298x over previous
#include <cuda_runtime.h>
#include <cuda_bf16.h>

// GraphGather / segment_sum, atomic-free:
//   out[b, :] = sum of feats[a, :] for membership[a] == b
// feats: [n_atoms, 128] f32, membership: [n_atoms] i32 (SORTED),
// out: [batch, 128] f32.
//
// membership sorted => segment b is rows [lower_bound(b), lower_bound(b+1)).
// One warp per segment: lanes 0/1 binary-search both bounds in parallel,
// lanes stream the rows as float4 (lane l owns features [4l,4l+4)),
// accumulate in registers, single coalesced STG.128 at the end.
// Empty segments naturally write zeros -> no separate zero-fill kernel,
// no atomics, no extra L2 RMW traffic.

#define N_FEAT 128
#define FEAT4 (N_FEAT / 4)   // 32 float4 per row -> one per lane
#define THREADS_PER_BLOCK 256

__global__ __launch_bounds__(THREADS_PER_BLOCK)
void gg_segsum_kernel(const float4* __restrict__ feats,
                      const int* __restrict__ memb,
                      float4* __restrict__ out,
                      int n_atoms, int batch) {
    const int warp_id = (blockIdx.x * THREADS_PER_BLOCK + threadIdx.x) >> 5;
    const int lane = threadIdx.x & 31;
    if (warp_id >= batch) return;

    const int b = warp_id;

    // Parallel binary search: lane 0 finds lower_bound(b),
    // lane 1 finds lower_bound(b+1). Other lanes duplicate lane 1's search.
    int tgt = b + min(lane, 1);
    int lo = 0, hi = n_atoms;
    #pragma unroll 1
    while (lo < hi) {
        int mid = (lo + hi) >> 1;
        if (__ldg(memb + mid) < tgt) lo = mid + 1;
        else hi = mid;
    }
    const unsigned mask = 0xFFFFFFFFu;
    int start = __shfl_sync(mask, lo, 0);
    int end   = __shfl_sync(mask, lo, 1);

    // Stream rows [start, end), coalesced: lane l reads float4 at column l.
    float4 a0 = make_float4(0.f, 0.f, 0.f, 0.f);
    float4 a1 = make_float4(0.f, 0.f, 0.f, 0.f);

    const float4* p = feats + (size_t)start * FEAT4 + lane;
    int r = start;
    // 2-way software pipeline for MLP; loads are evict-first (streaming).
    for (; r + 2 <= end; r += 2) {
        float4 v0 = __ldcs(p);
        float4 v1 = __ldcs(p + FEAT4);
        p += 2 * FEAT4;
        a0.x += v0.x; a0.y += v0.y; a0.z += v0.z; a0.w += v0.w;
        a1.x += v1.x; a1.y += v1.y; a1.z += v1.z; a1.w += v1.w;
    }
    if (r < end) {
        float4 v0 = __ldcs(p);
        a0.x += v0.x; a0.y += v0.y; a0.z += v0.z; a0.w += v0.w;
    }

    a0.x += a1.x; a0.y += a1.y; a0.z += a1.z; a0.w += a1.w;

    // One coalesced 128-bit store per lane; empty segments write zeros.
    out[(size_t)b * FEAT4 + lane] = a0;
}

extern "C" void kernel_launch(void* const* d_in, const int* in_sizes, int n_in,
                              void* d_out, int out_size) {
    const float* feats = (const float*)d_in[0];
    const int* memb = (const int*)d_in[1];
    float* out = (float*)d_out;

    const int n_atoms = in_sizes[1];          // 524288
    const int batch = out_size / N_FEAT;      // 16384

    const int warps_per_block = THREADS_PER_BLOCK / 32;
    const int blocks = (batch + warps_per_block - 1) / warps_per_block;
    gg_segsum_kernel<<<blocks, THREADS_PER_BLOCK>>>(
        (const float4*)feats, memb, (float4*)out, n_atoms, batch);
}

// round 3
// speedup vs baseline: 1.2081x; 1.1732x over previous
#include <cuda_runtime.h>
#include <cuda_bf16.h>

// GraphGather / segment_sum:
//   out[b, :] = sum of feats[a, :] for membership[a] == b
// feats: [524288, 128] f32, membership: [524288] i32 (SORTED), out: [16384, 128] f32.
//
// R3: R1's balanced fixed-rows-per-warp streamer, with
//  - float4 zero-fill kernel (poisoned output), exact-sized grid
//  - one coalesced membership load per warp (lane l reads memb[row0+l], shfl'd out)
//  - 4 batches of 8 unconditional LDG.E.128 -> MLP_p1=8, then flush pass
//  - boundary flushes via atomicAdd (REDG), ~1 boundary per warp on average.

#define N_FEAT 128
#define FEAT4 (N_FEAT / 4)       // 32 float4 per row
#define ROWS_PER_WARP 32
#define TPB 256

__global__ void gg_zero4_kernel(float4* __restrict__ out, int n4) {
    int i = blockIdx.x * blockDim.x + threadIdx.x;
    if (i < n4) out[i] = make_float4(0.f, 0.f, 0.f, 0.f);
}

__device__ __forceinline__ void gg_flush(float* __restrict__ out,
                                         int seg, int lane, const float4& acc) {
    float* o = out + (size_t)seg * N_FEAT + lane * 4;
    atomicAdd(o + 0, acc.x);
    atomicAdd(o + 1, acc.y);
    atomicAdd(o + 2, acc.z);
    atomicAdd(o + 3, acc.w);
}

__global__ __launch_bounds__(TPB)
void gg_segsum_kernel(const float4* __restrict__ feats,
                      const int* __restrict__ memb,
                      float* __restrict__ out,
                      int n_atoms) {
    const int warp_id = (blockIdx.x * TPB + threadIdx.x) >> 5;
    const int lane = threadIdx.x & 31;
    const unsigned FULL = 0xFFFFFFFFu;

    const int row0 = warp_id * ROWS_PER_WARP;
    if (row0 >= n_atoms) return;

    // One coalesced membership load for the warp's 32 rows.
    const int last = n_atoms - 1;
    int mrow = row0 + lane;
    int mlane = memb[mrow <= last ? mrow : last];

    const int nrows = (row0 + ROWS_PER_WARP <= n_atoms) ? ROWS_PER_WARP
                                                        : (n_atoms - row0);
    const float4* base = feats + (size_t)row0 * FEAT4 + lane;

    float4 acc = make_float4(0.f, 0.f, 0.f, 0.f);
    int cur = __shfl_sync(FULL, mlane, 0);

    if (nrows == ROWS_PER_WARP) {
        #pragma unroll
        for (int bt = 0; bt < 4; ++bt) {
            // 8 independent 128-bit loads, issued back-to-back (MLP_p1 = 8).
            float4 v[8];
            #pragma unroll
            for (int i = 0; i < 8; ++i)
                v[i] = __ldcs(base + (size_t)(bt * 8 + i) * FEAT4);

            #pragma unroll
            for (int i = 0; i < 8; ++i) {
                int m = __shfl_sync(FULL, mlane, bt * 8 + i);
                if (m != cur) {            // rare: ~1 boundary / warp
                    gg_flush(out, cur, lane, acc);
                    acc = make_float4(0.f, 0.f, 0.f, 0.f);
                    cur = m;
                }
                acc.x += v[i].x; acc.y += v[i].y;
                acc.z += v[i].z; acc.w += v[i].w;
            }
        }
    } else {
        for (int i = 0; i < nrows; ++i) {
            float4 v = __ldcs(base + (size_t)i * FEAT4);
            int m = __shfl_sync(FULL, mlane, i);
            if (m != cur) {
                gg_flush(out, cur, lane, acc);
                acc = make_float4(0.f, 0.f, 0.f, 0.f);
                cur = m;
            }
            acc.x += v.x; acc.y += v.y; acc.z += v.z; acc.w += v.w;
        }
    }

    gg_flush(out, cur, lane, acc);
}

extern "C" void kernel_launch(void* const* d_in, const int* in_sizes, int n_in,
                              void* d_out, int out_size) {
    const float* feats = (const float*)d_in[0];
    const int* memb = (const int*)d_in[1];
    float* out = (float*)d_out;

    const int n_atoms = in_sizes[1];      // 524288
    const int n4 = out_size / 4;          // 524288 float4

    gg_zero4_kernel<<<(n4 + TPB - 1) / TPB, TPB>>>((float4*)out, n4);

    const int n_warps = (n_atoms + ROWS_PER_WARP - 1) / ROWS_PER_WARP;
    const int blocks = (n_warps + (TPB / 32) - 1) / (TPB / 32);
    gg_segsum_kernel<<<blocks, TPB>>>((const float4*)feats, memb, out, n_atoms);
}